// round 16
// baseline (speedup 1.0000x reference)
#include <cuda_runtime.h>
#include <cuda_fp16.h>
#include <stdint.h>
#include <math.h>

#define B_      32
#define T_      128
#define IN_     512
#define OUT_    512
#define N_      128
#define WD_     64
#define R_      4
#define H_      512
#define IFACE_  471
#define GATES_  2048
#define EPS_    1e-6f
#define LINKS_  132
#define MS_     68
#define CL_     4

__device__ float  g_xz[B_ * T_ * GATES_];     // precomputed x_t @ Wx[0:512,:]
__device__ __half g_wlstm[768 * GATES_];      // rows 0-255: Wx rows 512-767 (reads); rows 256-767: Wh
__device__ __half g_wo[768 * OUT_];           // Wo in fp16
__device__ __half g_wif[512 * 480];           // Wif fp16, per-rank 120-col padded slices

struct Smem {
    float M[N_ * MS_];
    float link[N_ * LINKS_];
    float linkT[N_ * LINKS_];
    float act[1280];            // [512:768) reads | [768:1280) h
    float c[128];
    float zbuf[8192];
    float hz[512];              // reduced Wh-partial gates for next step (local col layout)
    float v[472];
    float usage[N_];
    float prec[N_];
    float ww[N_];
    float wr[R_ * N_];
    float Mnorm[N_];
    float skv[N_];
    int   ski[N_];
    float aalloc[N_];
    float cw[N_];
    float crs[R_ * N_];
    float fw[R_ * N_];
    float bw[R_ * N_];
    float erasev[WD_];
    float wvec[WD_];
    float rb[R_];
    float keynorm[R_];
    float modes[R_ * 3];
    float sc[8];
};

__device__ __forceinline__ float sigf(float x) { return 1.f / (1.f + expf(-x)); }
__device__ __forceinline__ float softplusf(float x) {
    return fmaxf(x, 0.f) + log1pf(expf(-fabsf(x)));
}
__device__ __forceinline__ float warp_sum(float v) {
    #pragma unroll
    for (int o = 16; o; o >>= 1) v += __shfl_xor_sync(0xffffffffu, v, o);
    return v;
}
__device__ __forceinline__ float warp_max(float v) {
    #pragma unroll
    for (int o = 16; o; o >>= 1) v = fmaxf(v, __shfl_xor_sync(0xffffffffu, v, o));
    return v;
}
__device__ __forceinline__ void cluster_sync_na() {
    asm volatile("barrier.cluster.arrive;" ::: "memory");
    asm volatile("barrier.cluster.wait;" ::: "memory");
}
__device__ __forceinline__ void bar_sync(int id, int nthreads) {
    asm volatile("bar.sync %0, %1;" :: "r"(id), "r"(nthreads) : "memory");
}
__device__ __forceinline__ float dsmem_ld(const float* p, int rank) {
    uint32_t la = (uint32_t)__cvta_generic_to_shared((void*)p);
    uint32_t ra;
    asm("mapa.shared::cluster.u32 %0, %1, %2;" : "=r"(ra) : "r"(la), "r"(rank));
    float val;
    asm volatile("ld.shared::cluster.f32 %0, [%1];" : "=f"(val) : "r"(ra));
    return val;
}
__device__ __forceinline__ float dot4(float4 a, float4 b) {
    return fmaf(a.x, b.x, fmaf(a.y, b.y, fmaf(a.z, b.z, a.w * b.w)));
}
// fp16x8 partial-dot helper: acc[8] += sv * w[0..7]
__device__ __forceinline__ void fma8h(const __half* wp, float sv,
                                      float& a0, float& a1, float& a2, float& a3,
                                      float& a4, float& a5, float& a6, float& a7) {
    uint4 w = *reinterpret_cast<const uint4*>(wp);
    const __half2* h2 = reinterpret_cast<const __half2*>(&w);
    float2 f0 = __half22float2(h2[0]);
    float2 f1 = __half22float2(h2[1]);
    float2 f2 = __half22float2(h2[2]);
    float2 f3 = __half22float2(h2[3]);
    a0 = fmaf(sv, f0.x, a0); a1 = fmaf(sv, f0.y, a1);
    a2 = fmaf(sv, f1.x, a2); a3 = fmaf(sv, f1.y, a3);
    a4 = fmaf(sv, f2.x, a4); a5 = fmaf(sv, f2.y, a5);
    a6 = fmaf(sv, f3.x, a6); a7 = fmaf(sv, f3.y, a7);
}

// ---------------- weight conversion kernels ----------------
__global__ void __launch_bounds__(1024) cvt_lstm(const float* __restrict__ Wx,
                                                 const float* __restrict__ Wh) {
    int idx2 = (blockIdx.x * 1024 + threadIdx.x) * 2;
    if (idx2 >= 768 * GATES_) return;
    int row = idx2 >> 11, col = idx2 & 2047;
    const float* src = (row < 256) ? (Wx + (size_t)(512 + row) * GATES_ + col)
                                   : (Wh + (size_t)(row - 256) * GATES_ + col);
    *reinterpret_cast<__half2*>(&g_wlstm[idx2]) = __floats2half2_rn(src[0], src[1]);
}
__global__ void __launch_bounds__(1024) cvt_wo(const float* __restrict__ Wo) {
    int idx2 = (blockIdx.x * 1024 + threadIdx.x) * 2;
    if (idx2 >= 768 * OUT_) return;
    *reinterpret_cast<__half2*>(&g_wo[idx2]) = __floats2half2_rn(Wo[idx2], Wo[idx2 + 1]);
}
__global__ void __launch_bounds__(1024) cvt_wif(const float* __restrict__ Wif) {
    int idx = blockIdx.x * 1024 + threadIdx.x;
    if (idx >= 512 * 480) return;
    int row = idx / 480, c = idx % 480;
    int rank = c / 120, cc = c % 120;
    int ncols = (rank < 3) ? 118 : 117;
    float val = (cc < ncols) ? Wif[(size_t)row * IFACE_ + rank * 118 + cc] : 0.f;
    g_wif[idx] = __float2half_rn(val);
}

// ---------------- precompute kernel: g_xz = x @ Wx[0:512,:] ----------------
__global__ void __launch_bounds__(256) xz_kernel(const float* __restrict__ x,
                                                 const float* __restrict__ Wx) {
    __shared__ float xsT[16][132];
    __shared__ float ws[16][132];
    const int rb = blockIdx.x * 128;
    const int cb = blockIdx.y * 128;
    const int tid = threadIdx.x;
    const int tr0 = (tid >> 4) * 4;
    const int tc0 = (tid & 15) * 4;

    float acc[8][8];
    #pragma unroll
    for (int i = 0; i < 8; i++)
        #pragma unroll
        for (int j = 0; j < 8; j++) acc[i][j] = 0.f;

    for (int kt = 0; kt < IN_; kt += 16) {
        #pragma unroll
        for (int l = 0; l < 2; l++) {
            int idx = tid + l * 256;
            int row = idx >> 2;
            int k4  = (idx & 3) * 4;
            float4 xv = *reinterpret_cast<const float4*>(&x[(size_t)(rb + row) * IN_ + kt + k4]);
            xsT[k4 + 0][row] = xv.x; xsT[k4 + 1][row] = xv.y;
            xsT[k4 + 2][row] = xv.z; xsT[k4 + 3][row] = xv.w;
        }
        #pragma unroll
        for (int l = 0; l < 2; l++) {
            int idx = tid + l * 256;
            int kk = idx >> 5;
            int c4 = (idx & 31) * 4;
            *reinterpret_cast<float4*>(&ws[kk][c4]) =
                *reinterpret_cast<const float4*>(&Wx[(size_t)(kt + kk) * GATES_ + cb + c4]);
        }
        __syncthreads();
        #pragma unroll
        for (int kk = 0; kk < 16; kk++) {
            float xr[8], wc[8];
            *reinterpret_cast<float4*>(&xr[0]) = *reinterpret_cast<float4*>(&xsT[kk][tr0]);
            *reinterpret_cast<float4*>(&xr[4]) = *reinterpret_cast<float4*>(&xsT[kk][tr0 + 64]);
            *reinterpret_cast<float4*>(&wc[0]) = *reinterpret_cast<float4*>(&ws[kk][tc0]);
            *reinterpret_cast<float4*>(&wc[4]) = *reinterpret_cast<float4*>(&ws[kk][tc0 + 64]);
            #pragma unroll
            for (int i = 0; i < 8; i++)
                #pragma unroll
                for (int j = 0; j < 8; j++)
                    acc[i][j] = fmaf(xr[i], wc[j], acc[i][j]);
        }
        __syncthreads();
    }
    #pragma unroll
    for (int i = 0; i < 8; i++) {
        int row = rb + ((i < 4) ? (tr0 + i) : (64 + tr0 + i - 4));
        float4* d0 = reinterpret_cast<float4*>(&g_xz[(size_t)row * GATES_ + cb + tc0]);
        float4* d1 = reinterpret_cast<float4*>(&g_xz[(size_t)row * GATES_ + cb + 64 + tc0]);
        *d0 = make_float4(acc[i][0], acc[i][1], acc[i][2], acc[i][3]);
        *d1 = make_float4(acc[i][4], acc[i][5], acc[i][6], acc[i][7]);
    }
}

// ---------------- main recurrent kernel ----------------
__global__ void __launch_bounds__(1024, 1) __cluster_dims__(CL_, 1, 1) dnc_kernel(
    const float* __restrict__ bl,
    const float* __restrict__ bif,
    const float* __restrict__ bo,
    float* __restrict__ out)
{
    extern __shared__ char smraw[];
    Smem& s = *reinterpret_cast<Smem*>(smraw);
    const int tid  = threadIdx.x;
    const int lane = tid & 31;
    const int wi   = tid >> 5;
    uint32_t krank_u;
    asm("mov.u32 %0, %%cluster_ctarank;" : "=r"(krank_u));
    const int k = (int)krank_u;
    const int b = blockIdx.x >> 2;

    for (int i = tid; i < N_ * MS_;    i += 1024) s.M[i]     = 0.f;
    for (int i = tid; i < N_ * LINKS_; i += 1024) { s.link[i] = 0.f; s.linkT[i] = 0.f; }
    for (int i = tid; i < 1280;        i += 1024) s.act[i]   = 0.f;
    if (tid < 128) s.c[tid] = 0.f;
    if (tid < 512) s.hz[tid] = 0.f;
    if (tid < N_) { s.usage[tid] = 0.f; s.prec[tid] = 0.f; s.ww[tid] = 0.f; s.Mnorm[tid] = 0.f; }
    for (int i = tid; i < R_ * N_; i += 1024) s.wr[i] = 0.f;
    __syncthreads();

    for (int t = 0; t < T_; t++) {
        float xz0 = 0.f, xz1 = 0.f, xz2 = 0.f, xz3 = 0.f;
        if (tid < 128) {
            const float* xzr = g_xz + (size_t)(b * T_ + t) * GATES_;
            int jg = k * 128 + tid;
            xz0 = xzr[jg]; xz1 = xzr[512 + jg]; xz2 = xzr[1024 + jg]; xz3 = xzr[1536 + jg];
        }

        // ==== P1': reads-part gates partials (tid<512) || out GEMM of t-1 (tid>=512) ====
        if (tid < 512) {
            const int g2   = tid & 63;
            const int part = tid >> 6;        // 0..7, 32 rows each
            const int gate = g2 >> 4;
            const int cg8  = (g2 & 15) * 8;
            const int colg = gate * 512 + k * 128 + cg8;
            float a0=0.f,a1=0.f,a2=0.f,a3=0.f,a4=0.f,a5=0.f,a6=0.f,a7=0.f;
            const int r0 = part * 32;
            #pragma unroll 8
            for (int i = r0; i < r0 + 32; i++)
                fma8h(&g_wlstm[(size_t)i * GATES_ + colg], s.act[512 + i],
                      a0, a1, a2, a3, a4, a5, a6, a7);
            const int cl = gate * 128 + cg8;
            *reinterpret_cast<float4*>(&s.zbuf[part * 512 + cl])     = make_float4(a0, a1, a2, a3);
            *reinterpret_cast<float4*>(&s.zbuf[part * 512 + cl + 4]) = make_float4(a4, a5, a6, a7);
        } else if (t > 0) {
            const int q    = tid - 512;
            const int grp  = q & 15;          // 16 col groups x 8
            const int part = q >> 4;          // 0..31, 24 rows each
            const int cg8  = grp * 8;
            const int colg = k * 128 + cg8;
            float a0=0.f,a1=0.f,a2=0.f,a3=0.f,a4=0.f,a5=0.f,a6=0.f,a7=0.f;
            const int r0 = part * 24;
            #pragma unroll 8
            for (int i = r0; i < r0 + 24; i++)
                fma8h(&g_wo[(size_t)i * OUT_ + colg], s.act[512 + i],
                      a0, a1, a2, a3, a4, a5, a6, a7);
            *reinterpret_cast<float4*>(&s.zbuf[4096 + part * 128 + cg8])     = make_float4(a0, a1, a2, a3);
            *reinterpret_cast<float4*>(&s.zbuf[4096 + part * 128 + cg8 + 4]) = make_float4(a4, a5, a6, a7);
        }
        __syncthreads();

        // ==== P2+P3: gate reduce (8 parts + hz) + pointwise (tid<128) || out reduce+store ====
        if (tid < 128) {
            const int j  = tid;
            const int jg = k * 128 + j;
            float z0 = s.hz[j], z1 = s.hz[128 + j], z2 = s.hz[256 + j], z3 = s.hz[384 + j];
            #pragma unroll
            for (int p = 0; p < 8; p++) {
                z0 += s.zbuf[p * 512 + j];
                z1 += s.zbuf[p * 512 + 128 + j];
                z2 += s.zbuf[p * 512 + 256 + j];
                z3 += s.zbuf[p * 512 + 384 + j];
            }
            float zi = z0 + xz0 + bl[jg];
            float zf = z1 + xz1 + bl[512 + jg];
            float zg = z2 + xz2 + bl[1024 + jg];
            float zo = z3 + xz3 + bl[1536 + jg];
            float cn = sigf(zf) * s.c[j] + sigf(zi) * tanhf(zg);
            s.c[j] = cn;
            s.act[768 + jg] = sigf(zo) * tanhf(cn);
        } else if (t > 0 && tid >= 512 && tid < 640) {
            const int o = tid - 512;
            float acc = bo[k * 128 + o];
            #pragma unroll
            for (int p = 0; p < 32; p++) acc += s.zbuf[4096 + p * 128 + o];
            out[(size_t)b * T_ * OUT_ + (size_t)(t - 1) * OUT_ + k * 128 + o] = acc;
        }
        cluster_sync_na();   // S1: h-slices ready
        if (tid < 128) {
            #pragma unroll
            for (int p = 0; p < CL_; p++)
                if (p != k) s.act[768 + p * 128 + tid] = dsmem_ld(&s.act[768 + p * 128 + tid], p);
        }
        __syncthreads();     // h(t) fully local everywhere

        // ================= SPLIT =================
        if (tid >= 512) {
            // ---- overlap group: Wh-GEMM for gates(t+1) across iface + X-chain ----
            const int tid2 = tid - 512;
            const int g2   = tid2 & 63;
            const int part = tid2 >> 6;       // 0..7, 64 rows each
            const int gate = g2 >> 4;
            const int cg8  = (g2 & 15) * 8;
            const int colg = gate * 512 + k * 128 + cg8;
            float a0=0.f,a1=0.f,a2=0.f,a3=0.f,a4=0.f,a5=0.f,a6=0.f,a7=0.f;
            const int r0 = part * 64;
            #pragma unroll 8
            for (int i = r0; i < r0 + 32; i++)
                fma8h(&g_wlstm[(size_t)(256 + i) * GATES_ + colg], s.act[768 + i],
                      a0, a1, a2, a3, a4, a5, a6, a7);
            cluster_sync_na();   // S2 (joined mid-GEMM)
            #pragma unroll 8
            for (int i = r0 + 32; i < r0 + 64; i++)
                fma8h(&g_wlstm[(size_t)(256 + i) * GATES_ + colg], s.act[768 + i],
                      a0, a1, a2, a3, a4, a5, a6, a7);
            const int cl = gate * 128 + cg8;
            *reinterpret_cast<float4*>(&s.zbuf[1920 + part * 512 + cl])     = make_float4(a0, a1, a2, a3);
            *reinterpret_cast<float4*>(&s.zbuf[1920 + part * 512 + cl + 4]) = make_float4(a4, a5, a6, a7);
            bar_sync(2, 512);
            {
                float acc = 0.f;
                #pragma unroll
                for (int p = 0; p < 8; p++) acc += s.zbuf[1920 + p * 512 + tid2];
                s.hz[tid2] = acc;
            }
        } else {
            // ---- main group: iface + memory phase, all barriers are bar.sync 1,512 ----
            // P4 iface partials: 240 threads, 15 groups x 16 parts x 32 rows
            if (tid < 240) {
                const int grp  = tid % 15;
                const int part = tid / 15;
                const int cg8  = grp * 8;
                float a0=0.f,a1=0.f,a2=0.f,a3=0.f,a4=0.f,a5=0.f,a6=0.f,a7=0.f;
                const int r0 = part * 32;
                #pragma unroll 8
                for (int i = r0; i < r0 + 32; i++)
                    fma8h(&g_wif[(size_t)i * 480 + k * 120 + cg8], s.act[768 + i],
                          a0, a1, a2, a3, a4, a5, a6, a7);
                *reinterpret_cast<float4*>(&s.zbuf[part * 120 + cg8])     = make_float4(a0, a1, a2, a3);
                *reinterpret_cast<float4*>(&s.zbuf[part * 120 + cg8 + 4]) = make_float4(a4, a5, a6, a7);
            }
            bar_sync(1, 512);
            {
                const int base  = k * 118;
                const int ncols = (k < 3) ? 118 : 117;
                if (tid < ncols) {
                    float acc = 0.f;
                    #pragma unroll 8
                    for (int p = 0; p < 16; p++) acc += s.zbuf[p * 120 + tid];
                    s.v[base + tid] = acc + bif[base + tid];
                }
            }
            cluster_sync_na();   // S2: all v-slices written cluster-wide
            if (tid < IFACE_) {
                const int owner = tid / 118;
                if (owner != k) s.v[tid] = dsmem_ld(&s.v[tid], owner);
            }
            bar_sync(1, 512);

            // X1
            if (tid < 128) {
                float f0 = sigf(s.v[453]), f1 = sigf(s.v[454]), f2 = sigf(s.v[455]), f3 = sigf(s.v[456]);
                float ret = (1.f - f0 * s.wr[tid]) * (1.f - f1 * s.wr[128 + tid])
                          * (1.f - f2 * s.wr[256 + tid]) * (1.f - f3 * s.wr[384 + tid]);
                float u = s.usage[tid], w0 = s.ww[tid];
                s.usage[tid] = (u + w0 - u * w0) * ret;
            } else if (tid < 256) {
                int n = tid - 128;
                const float4* mr = reinterpret_cast<const float4*>(&s.M[n * MS_]);
                const float4* kr = reinterpret_cast<const float4*>(&s.v[260]);
                float d = 0.f;
                #pragma unroll
                for (int q = 0; q < 16; q++) d += dot4(mr[q], kr[q]);
                s.cw[n] = d / (s.Mnorm[n] + EPS_);
            } else if (wi >= 8 && wi < 12) {
                int r = wi - 8;
                float kv = s.v[r * 64 + lane], kv2 = s.v[r * 64 + lane + 32];
                float ssum = warp_sum(kv * kv + kv2 * kv2);
                if (lane == 0) s.keynorm[r] = sqrtf(ssum);
            } else if (wi == 12) {
                float kv = s.v[260 + lane], kv2 = s.v[260 + lane + 32];
                float ssum = warp_sum(kv * kv + kv2 * kv2);
                if (lane == 0) s.sc[3] = sqrtf(ssum);
            } else if (tid >= 416 && tid < 480) {
                int w = tid - 416;
                s.erasev[w] = sigf(s.v[325 + w]);
                s.wvec[w]   = s.v[389 + w];
            } else if (tid >= 480 && tid < 484) {
                int r = tid - 480;
                float m0 = s.v[459 + 3 * r], m1 = s.v[460 + 3 * r], m2 = s.v[461 + 3 * r];
                float mx = fmaxf(m0, fmaxf(m1, m2));
                float e0 = expf(m0 - mx), e1 = expf(m1 - mx), e2 = expf(m2 - mx);
                float ssum = e0 + e1 + e2;
                s.modes[3 * r] = e0 / ssum; s.modes[3 * r + 1] = e1 / ssum; s.modes[3 * r + 2] = e2 / ssum;
            } else if (tid >= 484 && tid < 488) {
                int r = tid - 484;
                s.rb[r] = 1.f + softplusf(s.v[256 + r]);
            } else if (tid == 488) s.sc[0] = 1.f + softplusf(s.v[324]);
            else if (tid == 489) s.sc[1] = sigf(s.v[457]);
            else if (tid == 490) s.sc[2] = sigf(s.v[458]);
            bar_sync(1, 512);

            // X2: write softmax (warp0) || rank-sort (threads 128-255)
            if (wi == 0) {
                float tsc = s.sc[0] / (s.sc[3] + EPS_);
                float a0 = s.cw[lane] * tsc,      a1 = s.cw[lane + 32] * tsc;
                float a2 = s.cw[lane + 64] * tsc, a3 = s.cw[lane + 96] * tsc;
                float mx = warp_max(fmaxf(fmaxf(a0, a1), fmaxf(a2, a3)));
                float e0 = expf(a0 - mx), e1 = expf(a1 - mx), e2 = expf(a2 - mx), e3 = expf(a3 - mx);
                float su = warp_sum(e0 + e1 + e2 + e3);
                float inv = 1.f / su;
                s.cw[lane] = e0 * inv; s.cw[lane + 32] = e1 * inv;
                s.cw[lane + 64] = e2 * inv; s.cw[lane + 96] = e3 * inv;
            } else if (tid >= 128 && tid < 256) {
                int e = tid - 128;
                float ue = s.usage[e];
                int cnt = 0;
                #pragma unroll 8
                for (int j = 0; j < 128; j++) {
                    float uj = s.usage[j];
                    cnt += (uj < ue) || (uj == ue && j < e);
                }
                s.skv[cnt] = ue; s.ski[cnt] = e;
            }
            bar_sync(1, 512);

            // X3+X4: cumprod + alloc + ww + wsum (warp 0)
            if (wi == 0) {
                float running = 1.f;
                #pragma unroll
                for (int r = 0; r < 4; r++) {
                    float v0 = s.skv[r * 32 + lane];
                    int   ix = s.ski[r * 32 + lane];
                    float c = v0;
                    #pragma unroll
                    for (int off = 1; off < 32; off <<= 1) {
                        float tsh = __shfl_up_sync(0xffffffffu, c, off);
                        if (lane >= off) c *= tsh;
                    }
                    float excl_in = __shfl_up_sync(0xffffffffu, c, 1);
                    float excl = (lane == 0) ? running : excl_in * running;
                    s.aalloc[ix] = (1.f - v0) * excl;
                    running *= __shfl_sync(0xffffffffu, c, 31);
                }
                __syncwarp();
                float ag = s.sc[1], wg = s.sc[2];
                float w0v = 0.f, w1v = 0.f, w2v = 0.f, w3v = 0.f;
                w0v = wg * (ag * s.aalloc[lane]       + (1.f - ag) * s.cw[lane]);
                w1v = wg * (ag * s.aalloc[lane + 32]  + (1.f - ag) * s.cw[lane + 32]);
                w2v = wg * (ag * s.aalloc[lane + 64]  + (1.f - ag) * s.cw[lane + 64]);
                w3v = wg * (ag * s.aalloc[lane + 96]  + (1.f - ag) * s.cw[lane + 96]);
                s.ww[lane] = w0v; s.ww[lane + 32] = w1v;
                s.ww[lane + 64] = w2v; s.ww[lane + 96] = w3v;
                float ssum = warp_sum(w0v + w1v + w2v + w3v);
                if (lane == 0) s.sc[4] = ssum;
            }
            bar_sync(1, 512);

            // X5+X6: link+linkT (512 threads, 4x8 tiles) then M update + Mnorm
            {
                const int ti = (tid >> 4) * 4;      // 32 row-blocks
                const int tj = (tid & 15) * 8;      // 16 col-blocks of 8
                float wwi[4], nva[4][4], nvb[4][4];
                #pragma unroll
                for (int r = 0; r < 4; r++) wwi[r] = s.ww[ti + r];
                float4 wwj4a = *reinterpret_cast<const float4*>(&s.ww[tj]);
                float4 wwj4b = *reinterpret_cast<const float4*>(&s.ww[tj + 4]);
                float4 pj4a  = *reinterpret_cast<const float4*>(&s.prec[tj]);
                float4 pj4b  = *reinterpret_cast<const float4*>(&s.prec[tj + 4]);
                #pragma unroll
                for (int r = 0; r < 4; r++) {
                    float4 la = *reinterpret_cast<const float4*>(&s.link[(ti + r) * LINKS_ + tj]);
                    float4 lb = *reinterpret_cast<const float4*>(&s.link[(ti + r) * LINKS_ + tj + 4]);
                    nva[r][0] = (1.f - wwi[r] - wwj4a.x) * la.x + wwi[r] * pj4a.x;
                    nva[r][1] = (1.f - wwi[r] - wwj4a.y) * la.y + wwi[r] * pj4a.y;
                    nva[r][2] = (1.f - wwi[r] - wwj4a.z) * la.z + wwi[r] * pj4a.z;
                    nva[r][3] = (1.f - wwi[r] - wwj4a.w) * la.w + wwi[r] * pj4a.w;
                    nvb[r][0] = (1.f - wwi[r] - wwj4b.x) * lb.x + wwi[r] * pj4b.x;
                    nvb[r][1] = (1.f - wwi[r] - wwj4b.y) * lb.y + wwi[r] * pj4b.y;
                    nvb[r][2] = (1.f - wwi[r] - wwj4b.z) * lb.z + wwi[r] * pj4b.z;
                    nvb[r][3] = (1.f - wwi[r] - wwj4b.w) * lb.w + wwi[r] * pj4b.w;
                    #pragma unroll
                    for (int cc = 0; cc < 4; cc++) {
                        if (ti + r == tj + cc)     nva[r][cc] = 0.f;
                        if (ti + r == tj + 4 + cc) nvb[r][cc] = 0.f;
                    }
                    *reinterpret_cast<float4*>(&s.link[(ti + r) * LINKS_ + tj]) =
                        make_float4(nva[r][0], nva[r][1], nva[r][2], nva[r][3]);
                    *reinterpret_cast<float4*>(&s.link[(ti + r) * LINKS_ + tj + 4]) =
                        make_float4(nvb[r][0], nvb[r][1], nvb[r][2], nvb[r][3]);
                }
                #pragma unroll
                for (int cc = 0; cc < 4; cc++) {
                    *reinterpret_cast<float4*>(&s.linkT[(tj + cc) * LINKS_ + ti]) =
                        make_float4(nva[0][cc], nva[1][cc], nva[2][cc], nva[3][cc]);
                    *reinterpret_cast<float4*>(&s.linkT[(tj + 4 + cc) * LINKS_ + ti]) =
                        make_float4(nvb[0][cc], nvb[1][cc], nvb[2][cc], nvb[3][cc]);
                }
            }
            {
                const int row = tid >> 2, sub = tid & 3;
                const int w0 = sub * 16;
                float wwn = s.ww[row];
                float sq = 0.f;
                #pragma unroll
                for (int q = 0; q < 4; q++) {
                    float4 m  = *reinterpret_cast<const float4*>(&s.M[row * MS_ + w0 + q * 4]);
                    float4 ev = *reinterpret_cast<const float4*>(&s.erasev[w0 + q * 4]);
                    float4 wv = *reinterpret_cast<const float4*>(&s.wvec[w0 + q * 4]);
                    m.x = m.x * (1.f - wwn * ev.x) + wwn * wv.x;
                    m.y = m.y * (1.f - wwn * ev.y) + wwn * wv.y;
                    m.z = m.z * (1.f - wwn * ev.z) + wwn * wv.z;
                    m.w = m.w * (1.f - wwn * ev.w) + wwn * wv.w;
                    sq += m.x * m.x + m.y * m.y + m.z * m.z + m.w * m.w;
                    *reinterpret_cast<float4*>(&s.M[row * MS_ + w0 + q * 4]) = m;
                }
                sq += __shfl_xor_sync(0xffffffffu, sq, 1);
                sq += __shfl_xor_sync(0xffffffffu, sq, 2);
                if (sub == 0) s.Mnorm[row] = sqrtf(sq);
            }
            bar_sync(1, 512);

            // X7+X8: fw (0-127) | bw (128-255) | crs (256-383) | prec (warp 12)
            if (tid < 128) {
                const int i = tid;
                const float4* lr  = reinterpret_cast<const float4*>(&s.link[i * LINKS_]);
                const float4* w0p = reinterpret_cast<const float4*>(&s.wr[0]);
                const float4* w1p = reinterpret_cast<const float4*>(&s.wr[128]);
                const float4* w2p = reinterpret_cast<const float4*>(&s.wr[256]);
                const float4* w3p = reinterpret_cast<const float4*>(&s.wr[384]);
                float a0 = 0.f, a1 = 0.f, a2 = 0.f, a3 = 0.f;
                #pragma unroll 8
                for (int q = 0; q < 32; q++) {
                    float4 l4 = lr[q];
                    a0 += dot4(l4, w0p[q]); a1 += dot4(l4, w1p[q]);
                    a2 += dot4(l4, w2p[q]); a3 += dot4(l4, w3p[q]);
                }
                s.fw[i] = a0; s.fw[128 + i] = a1; s.fw[256 + i] = a2; s.fw[384 + i] = a3;
            } else if (tid < 256) {
                const int i = tid - 128;
                const float4* lr  = reinterpret_cast<const float4*>(&s.linkT[i * LINKS_]);
                const float4* w0p = reinterpret_cast<const float4*>(&s.wr[0]);
                const float4* w1p = reinterpret_cast<const float4*>(&s.wr[128]);
                const float4* w2p = reinterpret_cast<const float4*>(&s.wr[256]);
                const float4* w3p = reinterpret_cast<const float4*>(&s.wr[384]);
                float a0 = 0.f, a1 = 0.f, a2 = 0.f, a3 = 0.f;
                #pragma unroll 8
                for (int q = 0; q < 32; q++) {
                    float4 l4 = lr[q];
                    a0 += dot4(l4, w0p[q]); a1 += dot4(l4, w1p[q]);
                    a2 += dot4(l4, w2p[q]); a3 += dot4(l4, w3p[q]);
                }
                s.bw[i] = a0; s.bw[128 + i] = a1; s.bw[256 + i] = a2; s.bw[384 + i] = a3;
            } else if (tid < 384) {
                const int n = tid - 256;
                const float4* mr  = reinterpret_cast<const float4*>(&s.M[n * MS_]);
                const float4* k0p = reinterpret_cast<const float4*>(&s.v[0]);
                const float4* k1p = reinterpret_cast<const float4*>(&s.v[64]);
                const float4* k2p = reinterpret_cast<const float4*>(&s.v[128]);
                const float4* k3p = reinterpret_cast<const float4*>(&s.v[192]);
                float d0 = 0.f, d1 = 0.f, d2 = 0.f, d3 = 0.f;
                #pragma unroll 8
                for (int q = 0; q < 16; q++) {
                    float4 m4 = mr[q];
                    d0 += dot4(m4, k0p[q]); d1 += dot4(m4, k1p[q]);
                    d2 += dot4(m4, k2p[q]); d3 += dot4(m4, k3p[q]);
                }
                float base = 1.f / (s.Mnorm[n] + EPS_);
                s.crs[n]       = s.rb[0] * d0 * base / (s.keynorm[0] + EPS_);
                s.crs[128 + n] = s.rb[1] * d1 * base / (s.keynorm[1] + EPS_);
                s.crs[256 + n] = s.rb[2] * d2 * base / (s.keynorm[2] + EPS_);
                s.crs[384 + n] = s.rb[3] * d3 * base / (s.keynorm[3] + EPS_);
            } else if (wi == 12) {
                float ssum = s.sc[4];
                #pragma unroll
                for (int o = 0; o < 4; o++) {
                    int n = lane + o * 32;
                    s.prec[n] = (1.f - ssum) * s.prec[n] + s.ww[n];
                }
            }
            bar_sync(1, 512);

            // X9: per-r read softmax + wr (warps 0-3)
            if (wi < 4) {
                int r = wi;
                float a0 = s.crs[r * N_ + lane],      a1 = s.crs[r * N_ + lane + 32];
                float a2 = s.crs[r * N_ + lane + 64], a3 = s.crs[r * N_ + lane + 96];
                float mx = warp_max(fmaxf(fmaxf(a0, a1), fmaxf(a2, a3)));
                float e0 = expf(a0 - mx), e1 = expf(a1 - mx), e2 = expf(a2 - mx), e3 = expf(a3 - mx);
                float su = warp_sum(e0 + e1 + e2 + e3);
                float inv = 1.f / su;
                float m0 = s.modes[3 * r], m1 = s.modes[3 * r + 1], m2 = s.modes[3 * r + 2];
                #pragma unroll
                for (int o = 0; o < 4; o++) {
                    int n = lane + o * 32;
                    float cv = (o == 0 ? e0 : o == 1 ? e1 : o == 2 ? e2 : e3) * inv;
                    s.wr[r * 128 + n] = m0 * s.bw[r * 128 + n] + m1 * cv + m2 * s.fw[r * 128 + n];
                }
            }
            bar_sync(1, 512);

            // X11 direct: 256 threads, full dot into act
            if (tid < 256) {
                int r = tid >> 6, w = tid & 63;
                float acc = 0.f;
                #pragma unroll 4
                for (int n = 0; n < 128; n++)
                    acc = fmaf(s.wr[r * 128 + n], s.M[n * MS_ + w], acc);
                s.act[512 + tid] = acc;
            }
        }
        __syncthreads();   // join both groups
    }

    // ==== final out GEMM for t = T-1 (all 1024 threads) ====
    {
        const int grp  = tid & 15;
        const int part = tid >> 4;       // 0..63, 12 rows each
        const int cg8  = grp * 8;
        const int colg = k * 128 + cg8;
        float a0=0.f,a1=0.f,a2=0.f,a3=0.f,a4=0.f,a5=0.f,a6=0.f,a7=0.f;
        const int r0 = part * 12;
        #pragma unroll
        for (int i = r0; i < r0 + 12; i++)
            fma8h(&g_wo[(size_t)i * OUT_ + colg], s.act[512 + i],
                  a0, a1, a2, a3, a4, a5, a6, a7);
        *reinterpret_cast<float4*>(&s.zbuf[part * 128 + cg8])     = make_float4(a0, a1, a2, a3);
        *reinterpret_cast<float4*>(&s.zbuf[part * 128 + cg8 + 4]) = make_float4(a4, a5, a6, a7);
    }
    __syncthreads();
    if (tid < 128) {
        float acc = bo[k * 128 + tid];
        #pragma unroll
        for (int p = 0; p < 64; p++) acc += s.zbuf[p * 128 + tid];
        out[(size_t)b * T_ * OUT_ + (size_t)(T_ - 1) * OUT_ + k * 128 + tid] = acc;
    }
}

extern "C" void kernel_launch(void* const* d_in, const int* in_sizes, int n_in,
                              void* d_out, int out_size) {
    (void)in_sizes; (void)n_in; (void)out_size;
    const float* x   = (const float*)d_in[0];
    const float* Wx  = (const float*)d_in[1];
    const float* Wh  = (const float*)d_in[2];
    const float* bl  = (const float*)d_in[3];
    const float* Wif = (const float*)d_in[4];
    const float* bif = (const float*)d_in[5];
    const float* Wo  = (const float*)d_in[6];
    const float* bo  = (const float*)d_in[7];
    float* out = (float*)d_out;

    cvt_lstm<<<(768 * GATES_ / 2 + 1023) / 1024, 1024>>>(Wx, Wh);
    cvt_wo<<<(768 * OUT_ / 2 + 1023) / 1024, 1024>>>(Wo);
    cvt_wif<<<(512 * 480 + 1023) / 1024, 1024>>>(Wif);

    dim3 pg(B_ * T_ / 128, GATES_ / 128);
    xz_kernel<<<pg, 256>>>(x, Wx);

    cudaFuncSetAttribute(dnc_kernel, cudaFuncAttributeMaxDynamicSharedMemorySize,
                         (int)sizeof(Smem));
    dnc_kernel<<<B_ * CL_, 1024, sizeof(Smem)>>>(bl, bif, bo, out);
}